// round 1
// baseline (speedup 1.0000x reference)
#include <cuda_runtime.h>
#include <cstdint>
#include <math.h>

// ---------------------------------------------------------------------------
// RWKV forward, fp32 baseline.
//   tokens  = B*T = 4096 rows, E = 1024, 4E = 4096, D = 512
//   11 TimeMix blocks + layer-0 double ChannelMix + final LN.
// GEMMs are NT (C[m,n] = sum_k A[m,k] * W[n,k]) with fused epilogues.
// WKV is an exact chunked parallel scan (16 chunks x 64 steps).
// ---------------------------------------------------------------------------

#define E_DIM   1024
#define FOUR_E  4096
#define D_IN    512
#define BTOK    4096
#define T_LEN   1024
#define BATCH   4
#define NLAYER  11
#define NCHUNK  16
#define CHLEN   64

// scratch (device globals -- no allocation allowed)
__device__ float g_res[BTOK * E_DIM];
__device__ float g_xn [BTOK * E_DIM];
__device__ float g_k  [BTOK * E_DIM];
__device__ float g_r  [BTOK * E_DIM];
__device__ float g_y  [BTOK * E_DIM];
__device__ float g_h  [BTOK * FOUR_E];
__device__ float g_st [BATCH * NCHUNK * 3 * E_DIM];

// ---------------------------------------------------------------------------
// GEMM: C[M,N] = A[M,K] @ W[N,K]^T   (both row-major, K contiguous)
// Tiles: 128x64x16, 256 threads, 8x4 per-thread microtile.
// ---------------------------------------------------------------------------
#define BM 128
#define BN 64
#define BK 16

#define EPI_NONE   0
#define EPI_BIAS   1
#define EPI_RELUSQ 2
#define EPI_ADD    3
#define EPI_CMIX   4

template <int EPI>
__global__ __launch_bounds__(256)
void gemm_nt(const float* __restrict__ A, const float* __restrict__ W,
             float* __restrict__ C, int M, int N, int K,
             const float* __restrict__ bias,
             const float* __restrict__ Cin,
             const float* __restrict__ Rg)
{
    __shared__ float As[BK][BM + 4];
    __shared__ float Bs[BK][BN + 4];

    const int bm  = blockIdx.y * BM;
    const int bn  = blockIdx.x * BN;
    const int tid = threadIdx.x;
    const int tx  = tid & 15;   // n dir: 16 * 4
    const int ty  = tid >> 4;   // m dir: 16 * 8

    float acc[8][4];
#pragma unroll
    for (int i = 0; i < 8; i++)
#pragma unroll
        for (int j = 0; j < 4; j++) acc[i][j] = 0.f;

    for (int k0 = 0; k0 < K; k0 += BK) {
        // A tile: 128x16 = 512 float4, 2 per thread
#pragma unroll
        for (int i = 0; i < 2; i++) {
            int idx = tid + i * 256;
            int row = idx >> 2;
            int kq  = (idx & 3) << 2;
            float4 v = *reinterpret_cast<const float4*>(A + (size_t)(bm + row) * K + k0 + kq);
            As[kq + 0][row] = v.x; As[kq + 1][row] = v.y;
            As[kq + 2][row] = v.z; As[kq + 3][row] = v.w;
        }
        // W tile: 64x16 = 256 float4, 1 per thread
        {
            int row = tid >> 2;
            int kq  = (tid & 3) << 2;
            float4 v = *reinterpret_cast<const float4*>(W + (size_t)(bn + row) * K + k0 + kq);
            Bs[kq + 0][row] = v.x; Bs[kq + 1][row] = v.y;
            Bs[kq + 2][row] = v.z; Bs[kq + 3][row] = v.w;
        }
        __syncthreads();

#pragma unroll
        for (int kk = 0; kk < BK; kk++) {
            float4 a0 = *reinterpret_cast<const float4*>(&As[kk][ty * 8]);
            float4 a1 = *reinterpret_cast<const float4*>(&As[kk][ty * 8 + 4]);
            float4 b0 = *reinterpret_cast<const float4*>(&Bs[kk][tx * 4]);
            float a[8] = {a0.x, a0.y, a0.z, a0.w, a1.x, a1.y, a1.z, a1.w};
            float b[4] = {b0.x, b0.y, b0.z, b0.w};
#pragma unroll
            for (int i = 0; i < 8; i++)
#pragma unroll
                for (int j = 0; j < 4; j++)
                    acc[i][j] = fmaf(a[i], b[j], acc[i][j]);
        }
        __syncthreads();
    }

    const int col = bn + tx * 4;
#pragma unroll
    for (int i = 0; i < 8; i++) {
        int row = bm + ty * 8 + i;
        size_t idx = (size_t)row * N + col;
        float4 v;
        v.x = acc[i][0]; v.y = acc[i][1]; v.z = acc[i][2]; v.w = acc[i][3];
        if (EPI == EPI_BIAS) {
            float4 bb = *reinterpret_cast<const float4*>(bias + col);
            v.x += bb.x; v.y += bb.y; v.z += bb.z; v.w += bb.w;
        }
        if (EPI == EPI_RELUSQ) {
            v.x = v.x > 0.f ? v.x * v.x : 0.f;
            v.y = v.y > 0.f ? v.y * v.y : 0.f;
            v.z = v.z > 0.f ? v.z * v.z : 0.f;
            v.w = v.w > 0.f ? v.w * v.w : 0.f;
        }
        if (EPI == EPI_ADD) {
            float4 ci = *reinterpret_cast<const float4*>(Cin + idx);
            v.x += ci.x; v.y += ci.y; v.z += ci.z; v.w += ci.w;
        }
        if (EPI == EPI_CMIX) {
            float4 ci = *reinterpret_cast<const float4*>(Cin + idx);
            float4 rr = *reinterpret_cast<const float4*>(Rg + idx);
            v.x = ci.x + v.x * (1.f / (1.f + expf(-rr.x)));
            v.y = ci.y + v.y * (1.f / (1.f + expf(-rr.y)));
            v.z = ci.z + v.z * (1.f / (1.f + expf(-rr.z)));
            v.w = ci.w + v.w * (1.f / (1.f + expf(-rr.w)));
        }
        *reinterpret_cast<float4*>(C + idx) = v;
    }
}

// ---------------------------------------------------------------------------
// LayerNorm over E=1024, one row per block, 256 threads, float4 per thread.
// ---------------------------------------------------------------------------
__global__ __launch_bounds__(256)
void ln_kernel(const float* __restrict__ x, float* __restrict__ o,
               const float* __restrict__ g, const float* __restrict__ b)
{
    __shared__ float sm[18];
    const int row = blockIdx.x;
    const int t   = threadIdx.x;
    float4 v = reinterpret_cast<const float4*>(x + (size_t)row * E_DIM)[t];
    float s  = v.x + v.y + v.z + v.w;
    float ss = v.x * v.x + v.y * v.y + v.z * v.z + v.w * v.w;
#pragma unroll
    for (int off = 16; off > 0; off >>= 1) {
        s  += __shfl_xor_sync(0xffffffffu, s, off);
        ss += __shfl_xor_sync(0xffffffffu, ss, off);
    }
    const int wp = t >> 5, lane = t & 31;
    if (lane == 0) { sm[wp] = s; sm[8 + wp] = ss; }
    __syncthreads();
    if (t < 32) {
        s  = (t < 8) ? sm[t]     : 0.f;
        ss = (t < 8) ? sm[8 + t] : 0.f;
#pragma unroll
        for (int off = 4; off > 0; off >>= 1) {
            s  += __shfl_xor_sync(0xffffffffu, s, off);
            ss += __shfl_xor_sync(0xffffffffu, ss, off);
        }
        if (t == 0) {
            float mean = s * (1.f / E_DIM);
            float var  = ss * (1.f / E_DIM) - mean * mean;
            sm[16] = mean;
            sm[17] = rsqrtf(var + 1e-5f);
        }
    }
    __syncthreads();
    const float mean = sm[16], inv = sm[17];
    float4 gg = reinterpret_cast<const float4*>(g)[t];
    float4 bb = reinterpret_cast<const float4*>(b)[t];
    float4 ov;
    ov.x = (v.x - mean) * inv * gg.x + bb.x;
    ov.y = (v.y - mean) * inv * gg.y + bb.y;
    ov.z = (v.z - mean) * inv * gg.z + bb.z;
    ov.w = (v.w - mean) * inv * gg.w + bb.w;
    reinterpret_cast<float4*>(o + (size_t)row * E_DIM)[t] = ov;
}

// ---------------------------------------------------------------------------
// WKV recurrence, exact chunked 2-pass scan.
// State (aa, bb, pp) represents (aa*e^pp, bb*e^pp) in an exact semiring:
//   decay:  pp += w
//   merge:  p=max(p1,p2); a=e^{p1-p}a1+e^{p2-p}a2; b likewise.
// Pass 1: per-chunk transitions from zero state. Pass 2: prefix-combine the
// 16 chunk states serially (cheap), then replay the chunk emitting
// y_t = sigmoid(r_t) * (e1*aa + e2*v_t)/(e1*bb + e2), with v == r.
// ---------------------------------------------------------------------------
__global__ __launch_bounds__(128)
void wkv_pass1(const float* __restrict__ k, const float* __restrict__ v,
               const float* __restrict__ decay, float* __restrict__ st)
{
    const int e = blockIdx.x * blockDim.x + threadIdx.x;
    const int c = blockIdx.y, b = blockIdx.z;
    const float w = -expf(decay[e]);
    float aa = 0.f, bb = 0.f, pp = -1e38f;
    const size_t base = ((size_t)b * T_LEN + (size_t)c * CHLEN) * E_DIM + e;
    const float* kp = k + base;
    const float* vp = v + base;
#pragma unroll 4
    for (int t = 0; t < CHLEN; t++) {
        float kt = kp[(size_t)t * E_DIM];
        float vt = vp[(size_t)t * E_DIM];
        float ww = pp + w;
        float p  = fmaxf(ww, kt);
        float e1 = expf(ww - p);
        float e2 = expf(kt - p);
        aa = e1 * aa + e2 * vt;
        bb = e1 * bb + e2;
        pp = p;
    }
    float* s = st + ((size_t)(b * NCHUNK + c) * 3) * E_DIM + e;
    s[0] = aa; s[E_DIM] = bb; s[2 * E_DIM] = pp;
}

__global__ __launch_bounds__(128)
void wkv_pass2(const float* __restrict__ k, const float* __restrict__ v,
               const float* __restrict__ decay, const float* __restrict__ first,
               const float* __restrict__ st, float* __restrict__ y)
{
    const int e = blockIdx.x * blockDim.x + threadIdx.x;
    const int c = blockIdx.y, b = blockIdx.z;
    const float w = -expf(decay[e]);
    const float u = first[e];
    float aa = 0.f, bb = 0.f, pp = -1e38f;
    for (int j = 0; j < c; j++) {
        const float* s = st + ((size_t)(b * NCHUNK + j) * 3) * E_DIM + e;
        float pd = pp + (float)CHLEN * w;
        float a2 = s[0], b2 = s[E_DIM], p2 = s[2 * E_DIM];
        float p  = fmaxf(pd, p2);
        float e1 = expf(pd - p), e2 = expf(p2 - p);
        aa = e1 * aa + e2 * a2;
        bb = e1 * bb + e2 * b2;
        pp = p;
    }
    const size_t base = ((size_t)b * T_LEN + (size_t)c * CHLEN) * E_DIM + e;
    const float* kp = k + base;
    const float* vp = v + base;
    float* yp = y + base;
    for (int t = 0; t < CHLEN; t++) {
        float kt = kp[(size_t)t * E_DIM];
        float vt = vp[(size_t)t * E_DIM];   // v == r in this model
        float ww = u + kt;
        float p  = fmaxf(pp, ww);
        float e1 = expf(pp - p), e2 = expf(ww - p);
        float yt = (e1 * aa + e2 * vt) / (e1 * bb + e2);
        yp[(size_t)t * E_DIM] = yt * (1.f / (1.f + expf(-vt)));  // sigmoid(r)*wkv
        float ww2 = pp + w;
        float p2  = fmaxf(ww2, kt);
        e1 = expf(ww2 - p2); e2 = expf(kt - p2);
        aa = e1 * aa + e2 * vt;
        bb = e1 * bb + e2;
        pp = p2;
    }
}

// ---------------------------------------------------------------------------
// Host orchestration
// ---------------------------------------------------------------------------
extern "C" void kernel_launch(void* const* d_in, const int* in_sizes, int n_in,
                              void* d_out, int out_size)
{
    const float* inp    = (const float*)d_in[0];
    const float* W_in   = (const float*)d_in[1];
    const float* b_in   = (const float*)d_in[2];
    const float* ln0g   = (const float*)d_in[3];
    const float* ln0b   = (const float*)d_in[4];
    const float* l0ln1g = (const float*)d_in[5];
    const float* l0ln1b = (const float*)d_in[6];
    const float* l0ln2g = (const float*)d_in[7];
    const float* l0ln2b = (const float*)d_in[8];
    const float* l0cmk  = (const float*)d_in[9];
    const float* l0cmv  = (const float*)d_in[10];
    const float* l0cmr  = (const float*)d_in[11];
    const float* l0ffk  = (const float*)d_in[12];
    const float* l0ffv  = (const float*)d_in[13];
    const float* l0ffr  = (const float*)d_in[14];
    const float* tmk    = (const float*)d_in[15];
    const float* tmr    = (const float*)d_in[16];
    const float* tmo    = (const float*)d_in[17];
    const float* tmdec  = (const float*)d_in[18];
    const float* tmfst  = (const float*)d_in[19];
    const float* ln1g   = (const float*)d_in[20];
    const float* ln1b   = (const float*)d_in[21];
    const float* ln2g   = (const float*)d_in[22];
    const float* ln2b   = (const float*)d_in[23];
    const float* ffk    = (const float*)d_in[24];
    const float* ffv    = (const float*)d_in[25];
    const float* ffr    = (const float*)d_in[26];
    const float* outg   = (const float*)d_in[27];
    const float* outb   = (const float*)d_in[28];
    float* out = (float*)d_out;

    float *res, *xn, *kb, *rb, *yb, *hb, *st;
    cudaGetSymbolAddress((void**)&res, g_res);
    cudaGetSymbolAddress((void**)&xn,  g_xn);
    cudaGetSymbolAddress((void**)&kb,  g_k);
    cudaGetSymbolAddress((void**)&rb,  g_r);
    cudaGetSymbolAddress((void**)&yb,  g_y);
    cudaGetSymbolAddress((void**)&hb,  g_h);
    cudaGetSymbolAddress((void**)&st,  g_st);

    const dim3 gE  (E_DIM  / BN, BTOK / BM);  // (16, 32)
    const dim3 g4E (FOUR_E / BN, BTOK / BM);  // (64, 32)
    const dim3 gWKV(E_DIM / 128, NCHUNK, BATCH);

    // x = inputs @ W_in^T + b_in ; res = LN(x, ln0)
    gemm_nt<EPI_BIAS><<<gE, 256>>>(inp, W_in, xn, BTOK, E_DIM, D_IN, b_in, nullptr, nullptr);
    ln_kernel<<<BTOK, 256>>>(xn, res, ln0g, ln0b);

    // channel mix helper: res += sigmoid(LN(res)@Wr^T) * (relu(LN(res)@Wk^T)^2 @ Wv^T)
    auto cmix = [&](const float* lg, const float* lb,
                    const float* Wk, const float* Wv, const float* Wr) {
        ln_kernel<<<BTOK, 256>>>(res, xn, lg, lb);
        gemm_nt<EPI_RELUSQ><<<g4E, 256>>>(xn, Wk, hb, BTOK, FOUR_E, E_DIM, nullptr, nullptr, nullptr);
        gemm_nt<EPI_NONE  ><<<gE,  256>>>(xn, Wr, rb, BTOK, E_DIM,  E_DIM, nullptr, nullptr, nullptr);
        gemm_nt<EPI_CMIX  ><<<gE,  256>>>(hb, Wv, res, BTOK, E_DIM, FOUR_E, nullptr, res, rb);
    };

    // layer 0: two channel mixes (ffnpre)
    cmix(l0ln1g, l0ln1b, l0cmk, l0cmv, l0cmr);
    cmix(l0ln2g, l0ln2b, l0ffk, l0ffv, l0ffr);

    // layers 1..11: TimeMix + ChannelMix
    for (int l = 0; l < NLAYER; l++) {
        const size_t oEE = (size_t)l * E_DIM * E_DIM;
        const size_t o4E = (size_t)l * FOUR_E * E_DIM;
        const size_t oE  = (size_t)l * E_DIM;

        ln_kernel<<<BTOK, 256>>>(res, xn, ln1g + oE, ln1b + oE);
        gemm_nt<EPI_NONE><<<gE, 256>>>(xn, tmk + oEE, kb, BTOK, E_DIM, E_DIM, nullptr, nullptr, nullptr);
        gemm_nt<EPI_NONE><<<gE, 256>>>(xn, tmr + oEE, rb, BTOK, E_DIM, E_DIM, nullptr, nullptr, nullptr);
        wkv_pass1<<<gWKV, 128>>>(kb, rb, tmdec + oE, st);
        wkv_pass2<<<gWKV, 128>>>(kb, rb, tmdec + oE, tmfst + oE, st, yb);
        gemm_nt<EPI_ADD><<<gE, 256>>>(yb, tmo + oEE, res, BTOK, E_DIM, E_DIM, nullptr, res, nullptr);

        ln_kernel<<<BTOK, 256>>>(res, xn, ln2g + oE, ln2b + oE);
        gemm_nt<EPI_RELUSQ><<<g4E, 256>>>(xn, ffk + o4E, hb, BTOK, FOUR_E, E_DIM, nullptr, nullptr, nullptr);
        gemm_nt<EPI_NONE  ><<<gE,  256>>>(xn, ffr + oEE, rb, BTOK, E_DIM,  E_DIM, nullptr, nullptr, nullptr);
        gemm_nt<EPI_CMIX  ><<<gE,  256>>>(hb, ffv + o4E, res, BTOK, E_DIM, FOUR_E, nullptr, res, rb);
    }

    // final LN -> output
    ln_kernel<<<BTOK, 256>>>(res, out, outg, outb);
}

// round 3
// speedup vs baseline: 2.5826x; 2.5826x over previous
#include <cuda_runtime.h>
#include <cuda_bf16.h>
#include <cstdint>
#include <math.h>

// ---------------------------------------------------------------------------
// RWKV forward. GEMMs via legacy mma.sync (HMMA) bf16 hi/lo split, fp32 accum.
// (tcgen05 is unavailable: harness PTX target is compute_103, not 103a.)
//   tokens = 4096, E = 1024, 4E = 4096, D = 512, 11 TimeMix + layer0 + LN.
// ---------------------------------------------------------------------------

#define E_DIM   1024
#define FOUR_E  4096
#define D_IN    512
#define BTOK    4096
#define T_LEN   1024
#define BATCH   4
#define NLAYER  11
#define NCHUNK  16
#define CHLEN   64

// scratch (device globals -- no allocation allowed)
__device__ float g_res[BTOK * E_DIM];
__device__ float g_xn [BTOK * E_DIM];
__device__ float g_k  [BTOK * E_DIM];
__device__ float g_r  [BTOK * E_DIM];
__device__ float g_y  [BTOK * E_DIM];
__device__ float g_h  [BTOK * FOUR_E];
__device__ float g_st [BATCH * NCHUNK * 3 * E_DIM];

// ---------------------------------------------------------------------------
// MMA GEMM: C[M,N] = A[M,K] @ W[N,K]^T, fp32 in/out.
// CTA 128x128x32, 512 threads (16 warps, 4x4), warp tile 32x32.
// bf16 split: A = Ah + Al (Ah = truncation, Al exact-ish residual), same for W.
// C += Ah*Bh + Ah*Bl + Al*Bh   (Al*Bl dropped, ~2^-17 relative)
// ---------------------------------------------------------------------------
#define TM 128
#define TN 128
#define TK 32
#define GT 512

#define ROWB 80                      // bf16 row: 32*2=64B data + 16B pad
#define OFF_AH 0
#define OFF_AL (128 * ROWB)          // 10240
#define OFF_BH (2 * 128 * ROWB)      // 20480
#define OFF_BL (3 * 128 * ROWB)      // 30720
#define BUF_SZ (4 * 128 * ROWB)      // 40960
#define GEMM_SMEM (2 * BUF_SZ)       // 81920

#define EPI_NONE   0
#define EPI_BIAS   1
#define EPI_RELUSQ 2
#define EPI_ADD    3
#define EPI_CMIX   4

__device__ __forceinline__ uint32_t smem_u32(const void* p) {
    uint32_t a;
    asm("{ .reg .u64 t; cvta.to.shared.u64 t, %1; cvt.u32.u64 %0, t; }" : "=r"(a) : "l"(p));
    return a;
}

__device__ __forceinline__ void ldm_x4(uint32_t* r, uint32_t addr) {
    asm volatile("ldmatrix.sync.aligned.m8n8.x4.shared.b16 {%0,%1,%2,%3}, [%4];"
        : "=r"(r[0]), "=r"(r[1]), "=r"(r[2]), "=r"(r[3]) : "r"(addr));
}

__device__ __forceinline__ void mma_bf16(float* d, const uint32_t* a, uint32_t b0, uint32_t b1) {
    asm volatile("mma.sync.aligned.m16n8k16.row.col.f32.bf16.bf16.f32 "
        "{%0,%1,%2,%3}, {%4,%5,%6,%7}, {%8,%9}, {%0,%1,%2,%3};"
        : "+f"(d[0]), "+f"(d[1]), "+f"(d[2]), "+f"(d[3])
        : "r"(a[0]), "r"(a[1]), "r"(a[2]), "r"(a[3]), "r"(b0), "r"(b1));
}

// convert float4 -> hi bf16x2 pair (truncated) + lo bf16x2 pair (residual)
__device__ __forceinline__ void split4(float4 v, uint32_t& h01, uint32_t& h23,
                                       uint32_t& l01, uint32_t& l23) {
    uint32_t bx = __float_as_uint(v.x), by = __float_as_uint(v.y);
    uint32_t bz = __float_as_uint(v.z), bw = __float_as_uint(v.w);
    h01 = __byte_perm(bx, by, 0x7632);
    h23 = __byte_perm(bz, bw, 0x7632);
    float lx = v.x - __uint_as_float(bx & 0xFFFF0000u);
    float ly = v.y - __uint_as_float(by & 0xFFFF0000u);
    float lz = v.z - __uint_as_float(bz & 0xFFFF0000u);
    float lw = v.w - __uint_as_float(bw & 0xFFFF0000u);
    asm("cvt.rn.bf16x2.f32 %0, %1, %2;" : "=r"(l01) : "f"(ly), "f"(lx));
    asm("cvt.rn.bf16x2.f32 %0, %1, %2;" : "=r"(l23) : "f"(lw), "f"(lz));
}

__device__ __forceinline__ void sts64(uint32_t addr, uint32_t a, uint32_t b) {
    asm volatile("st.shared.v2.u32 [%0], {%1, %2};" :: "r"(addr), "r"(a), "r"(b));
}

template <int EPI>
__global__ __launch_bounds__(GT, 1)
void gemm_mma(const float* __restrict__ A, const float* __restrict__ W,
              float* __restrict__ C, int M, int N, int K,
              const float* __restrict__ bias,
              const float* __restrict__ Cin,
              const float* __restrict__ Rg)
{
    extern __shared__ char smem[];
    const uint32_t sbase = smem_u32(smem);
    const int tid  = threadIdx.x;
    const int lane = tid & 31;
    const int wid  = tid >> 5;
    const int wm   = wid & 3;   // warp m index (0..3)
    const int wn   = wid >> 2;  // warp n index (0..3)
    const int bm   = blockIdx.y * TM;
    const int bn   = blockIdx.x * TN;

    // per-thread load slots: 2 float4 from A, 2 from W, per stage
    // A tile 128x32 fp32 = 1024 float4; idx -> row=idx>>3, q=idx&7
    const int a_row0 = (tid + 0)   >> 3, a_q0 = (tid + 0)   & 7;
    const int a_row1 = (tid + 512) >> 3, a_q1 = (tid + 512) & 7;

    float acc[2][4][4];
#pragma unroll
    for (int i = 0; i < 2; i++)
#pragma unroll
        for (int j = 0; j < 4; j++)
#pragma unroll
            for (int q = 0; q < 4; q++) acc[i][j][q] = 0.f;

    const int S = K / TK;

    // ldmatrix source addresses (depend only on lane)
    const int lrow  = lane & 15;
    const int lchun = lane >> 4;   // 0 or 1 -> +8 in k

    auto stage_store = [&](int buf, const float4& va0, const float4& va1,
                           const float4& vb0, const float4& vb1) {
        const uint32_t sb = sbase + buf * BUF_SZ;
        uint32_t h01, h23, l01, l23;
        split4(va0, h01, h23, l01, l23);
        sts64(sb + OFF_AH + a_row0 * ROWB + a_q0 * 8, h01, h23);
        sts64(sb + OFF_AL + a_row0 * ROWB + a_q0 * 8, l01, l23);
        split4(va1, h01, h23, l01, l23);
        sts64(sb + OFF_AH + a_row1 * ROWB + a_q1 * 8, h01, h23);
        sts64(sb + OFF_AL + a_row1 * ROWB + a_q1 * 8, l01, l23);
        split4(vb0, h01, h23, l01, l23);
        sts64(sb + OFF_BH + a_row0 * ROWB + a_q0 * 8, h01, h23);
        sts64(sb + OFF_BL + a_row0 * ROWB + a_q0 * 8, l01, l23);
        split4(vb1, h01, h23, l01, l23);
        sts64(sb + OFF_BH + a_row1 * ROWB + a_q1 * 8, h01, h23);
        sts64(sb + OFF_BL + a_row1 * ROWB + a_q1 * 8, l01, l23);
    };

    auto load_g = [&](int s, float4& va0, float4& va1, float4& vb0, float4& vb1) {
        const int k0 = s * TK;
        va0 = *reinterpret_cast<const float4*>(A + (size_t)(bm + a_row0) * K + k0 + a_q0 * 4);
        va1 = *reinterpret_cast<const float4*>(A + (size_t)(bm + a_row1) * K + k0 + a_q1 * 4);
        vb0 = *reinterpret_cast<const float4*>(W + (size_t)(bn + a_row0) * K + k0 + a_q0 * 4);
        vb1 = *reinterpret_cast<const float4*>(W + (size_t)(bn + a_row1) * K + k0 + a_q1 * 4);
    };

    // prologue
    {
        float4 va0, va1, vb0, vb1;
        load_g(0, va0, va1, vb0, vb1);
        stage_store(0, va0, va1, vb0, vb1);
    }
    __syncthreads();

    for (int s = 0; s < S; s++) {
        const int buf = s & 1;
        float4 va0, va1, vb0, vb1;
        if (s + 1 < S) load_g(s + 1, va0, va1, vb0, vb1);

        const uint32_t sb = sbase + buf * BUF_SZ;
#pragma unroll
        for (int kk = 0; kk < 2; kk++) {
            const uint32_t chunk_off = (uint32_t)((kk * 2 + lchun) * 16);
            uint32_t ah[2][4], al[2][4], bh[2][4], bl[2][4];
#pragma unroll
            for (int mt = 0; mt < 2; mt++) {
                uint32_t ad = sb + OFF_AH + (uint32_t)((wm * 32 + mt * 16 + lrow) * ROWB) + chunk_off;
                ldm_x4(ah[mt], ad);
                ldm_x4(al[mt], ad + (OFF_AL - OFF_AH));
            }
#pragma unroll
            for (int bt = 0; bt < 2; bt++) {
                uint32_t bd = sb + OFF_BH + (uint32_t)((wn * 32 + bt * 16 + lrow) * ROWB) + chunk_off;
                ldm_x4(bh[bt], bd);
                ldm_x4(bl[bt], bd + (OFF_BL - OFF_BH));
            }
#pragma unroll
            for (int mt = 0; mt < 2; mt++)
#pragma unroll
                for (int bt = 0; bt < 2; bt++)
#pragma unroll
                    for (int j = 0; j < 2; j++) {
                        const int nt = bt * 2 + j;
                        mma_bf16(acc[mt][nt], ah[mt], bh[bt][j], bh[bt][2 + j]);
                        mma_bf16(acc[mt][nt], ah[mt], bl[bt][j], bl[bt][2 + j]);
                        mma_bf16(acc[mt][nt], al[mt], bh[bt][j], bh[bt][2 + j]);
                    }
        }

        if (s + 1 < S) stage_store(buf ^ 1, va0, va1, vb0, vb1);
        __syncthreads();
    }

    // epilogue: c0,c1 at (row, col), c2,c3 at (row+8, col)
#pragma unroll
    for (int mt = 0; mt < 2; mt++)
#pragma unroll
        for (int nt = 0; nt < 4; nt++) {
            const int row = bm + wm * 32 + mt * 16 + (lane >> 2);
            const int col = bn + wn * 32 + nt * 8 + (lane & 3) * 2;
#pragma unroll
            for (int h = 0; h < 2; h++) {
                const int r = row + h * 8;
                const size_t idx = (size_t)r * N + col;
                float2 v = make_float2(acc[mt][nt][2 * h + 0], acc[mt][nt][2 * h + 1]);
                if (EPI == EPI_BIAS) {
                    float2 bb = *reinterpret_cast<const float2*>(bias + col);
                    v.x += bb.x; v.y += bb.y;
                }
                if (EPI == EPI_RELUSQ) {
                    v.x = v.x > 0.f ? v.x * v.x : 0.f;
                    v.y = v.y > 0.f ? v.y * v.y : 0.f;
                }
                if (EPI == EPI_ADD) {
                    float2 ci = *reinterpret_cast<const float2*>(Cin + idx);
                    v.x += ci.x; v.y += ci.y;
                }
                if (EPI == EPI_CMIX) {
                    float2 ci = *reinterpret_cast<const float2*>(Cin + idx);
                    float2 rr = *reinterpret_cast<const float2*>(Rg + idx);
                    v.x = ci.x + v.x * (1.f / (1.f + expf(-rr.x)));
                    v.y = ci.y + v.y * (1.f / (1.f + expf(-rr.y)));
                }
                *reinterpret_cast<float2*>(C + idx) = v;
            }
        }
}

// ---------------------------------------------------------------------------
// LayerNorm over E=1024, one row per block, 256 threads, float4 per thread.
// ---------------------------------------------------------------------------
__global__ __launch_bounds__(256)
void ln_kernel(const float* __restrict__ x, float* __restrict__ o,
               const float* __restrict__ g, const float* __restrict__ b)
{
    __shared__ float sm[18];
    const int row = blockIdx.x;
    const int t   = threadIdx.x;
    float4 v = reinterpret_cast<const float4*>(x + (size_t)row * E_DIM)[t];
    float s  = v.x + v.y + v.z + v.w;
    float ss = v.x * v.x + v.y * v.y + v.z * v.z + v.w * v.w;
#pragma unroll
    for (int off = 16; off > 0; off >>= 1) {
        s  += __shfl_xor_sync(0xffffffffu, s, off);
        ss += __shfl_xor_sync(0xffffffffu, ss, off);
    }
    const int wp = t >> 5, lane = t & 31;
    if (lane == 0) { sm[wp] = s; sm[8 + wp] = ss; }
    __syncthreads();
    if (t < 32) {
        s  = (t < 8) ? sm[t]     : 0.f;
        ss = (t < 8) ? sm[8 + t] : 0.f;
#pragma unroll
        for (int off = 4; off > 0; off >>= 1) {
            s  += __shfl_xor_sync(0xffffffffu, s, off);
            ss += __shfl_xor_sync(0xffffffffu, ss, off);
        }
        if (t == 0) {
            float mean = s * (1.f / E_DIM);
            float var  = ss * (1.f / E_DIM) - mean * mean;
            sm[16] = mean;
            sm[17] = rsqrtf(var + 1e-5f);
        }
    }
    __syncthreads();
    const float mean = sm[16], inv = sm[17];
    float4 gg = reinterpret_cast<const float4*>(g)[t];
    float4 bb = reinterpret_cast<const float4*>(b)[t];
    float4 ov;
    ov.x = (v.x - mean) * inv * gg.x + bb.x;
    ov.y = (v.y - mean) * inv * gg.y + bb.y;
    ov.z = (v.z - mean) * inv * gg.z + bb.z;
    ov.w = (v.w - mean) * inv * gg.w + bb.w;
    reinterpret_cast<float4*>(o + (size_t)row * E_DIM)[t] = ov;
}

// ---------------------------------------------------------------------------
// WKV recurrence, exact chunked 2-pass scan.
// ---------------------------------------------------------------------------
__global__ __launch_bounds__(128)
void wkv_pass1(const float* __restrict__ k, const float* __restrict__ v,
               const float* __restrict__ decay, float* __restrict__ st)
{
    const int e = blockIdx.x * blockDim.x + threadIdx.x;
    const int c = blockIdx.y, b = blockIdx.z;
    const float w = -expf(decay[e]);
    float aa = 0.f, bb = 0.f, pp = -1e38f;
    const size_t base = ((size_t)b * T_LEN + (size_t)c * CHLEN) * E_DIM + e;
    const float* kp = k + base;
    const float* vp = v + base;
#pragma unroll 4
    for (int t = 0; t < CHLEN; t++) {
        float kt = kp[(size_t)t * E_DIM];
        float vt = vp[(size_t)t * E_DIM];
        float ww = pp + w;
        float p  = fmaxf(ww, kt);
        float e1 = expf(ww - p);
        float e2 = expf(kt - p);
        aa = e1 * aa + e2 * vt;
        bb = e1 * bb + e2;
        pp = p;
    }
    float* s = st + ((size_t)(b * NCHUNK + c) * 3) * E_DIM + e;
    s[0] = aa; s[E_DIM] = bb; s[2 * E_DIM] = pp;
}

__global__ __launch_bounds__(128)
void wkv_pass2(const float* __restrict__ k, const float* __restrict__ v,
               const float* __restrict__ decay, const float* __restrict__ first,
               const float* __restrict__ st, float* __restrict__ y)
{
    const int e = blockIdx.x * blockDim.x + threadIdx.x;
    const int c = blockIdx.y, b = blockIdx.z;
    const float w = -expf(decay[e]);
    const float u = first[e];
    float aa = 0.f, bb = 0.f, pp = -1e38f;
    for (int j = 0; j < c; j++) {
        const float* s = st + ((size_t)(b * NCHUNK + j) * 3) * E_DIM + e;
        float pd = pp + (float)CHLEN * w;
        float a2 = s[0], b2 = s[E_DIM], p2 = s[2 * E_DIM];
        float p  = fmaxf(pd, p2);
        float e1 = expf(pd - p), e2 = expf(p2 - p);
        aa = e1 * aa + e2 * a2;
        bb = e1 * bb + e2 * b2;
        pp = p;
    }
    const size_t base = ((size_t)b * T_LEN + (size_t)c * CHLEN) * E_DIM + e;
    const float* kp = k + base;
    const float* vp = v + base;
    float* yp = y + base;
    for (int t = 0; t < CHLEN; t++) {
        float kt = kp[(size_t)t * E_DIM];
        float vt = vp[(size_t)t * E_DIM];   // v == r in this model
        float ww = u + kt;
        float p  = fmaxf(pp, ww);
        float e1 = expf(pp - p), e2 = expf(ww - p);
        float yt = (e1 * aa + e2 * vt) / (e1 * bb + e2);
        yp[(size_t)t * E_DIM] = yt * (1.f / (1.f + expf(-vt)));
        float ww2 = pp + w;
        float p2  = fmaxf(ww2, kt);
        e1 = expf(ww2 - p2); e2 = expf(kt - p2);
        aa = e1 * aa + e2 * vt;
        bb = e1 * bb + e2;
        pp = p2;
    }
}

// ---------------------------------------------------------------------------
// Host orchestration
// ---------------------------------------------------------------------------
static void set_smem_attrs() {
    cudaFuncSetAttribute(gemm_mma<EPI_NONE>,   cudaFuncAttributeMaxDynamicSharedMemorySize, GEMM_SMEM);
    cudaFuncSetAttribute(gemm_mma<EPI_BIAS>,   cudaFuncAttributeMaxDynamicSharedMemorySize, GEMM_SMEM);
    cudaFuncSetAttribute(gemm_mma<EPI_RELUSQ>, cudaFuncAttributeMaxDynamicSharedMemorySize, GEMM_SMEM);
    cudaFuncSetAttribute(gemm_mma<EPI_ADD>,    cudaFuncAttributeMaxDynamicSharedMemorySize, GEMM_SMEM);
    cudaFuncSetAttribute(gemm_mma<EPI_CMIX>,   cudaFuncAttributeMaxDynamicSharedMemorySize, GEMM_SMEM);
}

extern "C" void kernel_launch(void* const* d_in, const int* in_sizes, int n_in,
                              void* d_out, int out_size)
{
    const float* inp    = (const float*)d_in[0];
    const float* W_in   = (const float*)d_in[1];
    const float* b_in   = (const float*)d_in[2];
    const float* ln0g   = (const float*)d_in[3];
    const float* ln0b   = (const float*)d_in[4];
    const float* l0ln1g = (const float*)d_in[5];
    const float* l0ln1b = (const float*)d_in[6];
    const float* l0ln2g = (const float*)d_in[7];
    const float* l0ln2b = (const float*)d_in[8];
    const float* l0cmk  = (const float*)d_in[9];
    const float* l0cmv  = (const float*)d_in[10];
    const float* l0cmr  = (const float*)d_in[11];
    const float* l0ffk  = (const float*)d_in[12];
    const float* l0ffv  = (const float*)d_in[13];
    const float* l0ffr  = (const float*)d_in[14];
    const float* tmk    = (const float*)d_in[15];
    const float* tmr    = (const float*)d_in[16];
    const float* tmo    = (const float*)d_in[17];
    const float* tmdec  = (const float*)d_in[18];
    const float* tmfst  = (const float*)d_in[19];
    const float* ln1g   = (const float*)d_in[20];
    const float* ln1b   = (const float*)d_in[21];
    const float* ln2g   = (const float*)d_in[22];
    const float* ln2b   = (const float*)d_in[23];
    const float* ffk    = (const float*)d_in[24];
    const float* ffv    = (const float*)d_in[25];
    const float* ffr    = (const float*)d_in[26];
    const float* outg   = (const float*)d_in[27];
    const float* outb   = (const float*)d_in[28];
    float* out = (float*)d_out;

    set_smem_attrs();

    float *res, *xn, *kb, *rb, *yb, *hb, *st;
    cudaGetSymbolAddress((void**)&res, g_res);
    cudaGetSymbolAddress((void**)&xn,  g_xn);
    cudaGetSymbolAddress((void**)&kb,  g_k);
    cudaGetSymbolAddress((void**)&rb,  g_r);
    cudaGetSymbolAddress((void**)&yb,  g_y);
    cudaGetSymbolAddress((void**)&hb,  g_h);
    cudaGetSymbolAddress((void**)&st,  g_st);

    const dim3 gE  (E_DIM  / TN, BTOK / TM);  // (8, 32)
    const dim3 g4E (FOUR_E / TN, BTOK / TM);  // (32, 32)
    const dim3 gWKV(E_DIM / 128, NCHUNK, BATCH);

    // x = inputs @ W_in^T + b_in ; res = LN(x, ln0)
    gemm_mma<EPI_BIAS><<<gE, GT, GEMM_SMEM>>>(inp, W_in, xn, BTOK, E_DIM, D_IN, b_in, nullptr, nullptr);
    ln_kernel<<<BTOK, 256>>>(xn, res, ln0g, ln0b);

    auto cmix = [&](const float* lg, const float* lb,
                    const float* Wk, const float* Wv, const float* Wr) {
        ln_kernel<<<BTOK, 256>>>(res, xn, lg, lb);
        gemm_mma<EPI_RELUSQ><<<g4E, GT, GEMM_SMEM>>>(xn, Wk, hb, BTOK, FOUR_E, E_DIM, nullptr, nullptr, nullptr);
        gemm_mma<EPI_NONE  ><<<gE,  GT, GEMM_SMEM>>>(xn, Wr, rb, BTOK, E_DIM,  E_DIM, nullptr, nullptr, nullptr);
        gemm_mma<EPI_CMIX  ><<<gE,  GT, GEMM_SMEM>>>(hb, Wv, res, BTOK, E_DIM, FOUR_E, nullptr, res, rb);
    };

    cmix(l0ln1g, l0ln1b, l0cmk, l0cmv, l0cmr);
    cmix(l0ln2g, l0ln2b, l0ffk, l0ffv, l0ffr);

    for (int l = 0; l < NLAYER; l++) {
        const size_t oEE = (size_t)l * E_DIM * E_DIM;
        const size_t o4E = (size_t)l * FOUR_E * E_DIM;
        const size_t oE  = (size_t)l * E_DIM;

        ln_kernel<<<BTOK, 256>>>(res, xn, ln1g + oE, ln1b + oE);
        gemm_mma<EPI_NONE><<<gE, GT, GEMM_SMEM>>>(xn, tmk + oEE, kb, BTOK, E_DIM, E_DIM, nullptr, nullptr, nullptr);
        gemm_mma<EPI_NONE><<<gE, GT, GEMM_SMEM>>>(xn, tmr + oEE, rb, BTOK, E_DIM, E_DIM, nullptr, nullptr, nullptr);
        wkv_pass1<<<gWKV, 128>>>(kb, rb, tmdec + oE, st);
        wkv_pass2<<<gWKV, 128>>>(kb, rb, tmdec + oE, tmfst + oE, st, yb);
        gemm_mma<EPI_ADD><<<gE, GT, GEMM_SMEM>>>(yb, tmo + oEE, res, BTOK, E_DIM, E_DIM, nullptr, res, nullptr);

        ln_kernel<<<BTOK, 256>>>(res, xn, ln2g + oE, ln2b + oE);
        gemm_mma<EPI_RELUSQ><<<g4E, GT, GEMM_SMEM>>>(xn, ffk + o4E, hb, BTOK, FOUR_E, E_DIM, nullptr, nullptr, nullptr);
        gemm_mma<EPI_NONE  ><<<gE,  GT, GEMM_SMEM>>>(xn, ffr + oEE, rb, BTOK, E_DIM,  E_DIM, nullptr, nullptr, nullptr);
        gemm_mma<EPI_CMIX  ><<<gE,  GT, GEMM_SMEM>>>(hb, ffv + o4E, res, BTOK, E_DIM, FOUR_E, nullptr, res, rb);
    }

    ln_kernel<<<BTOK, 256>>>(res, out, outg, outb);
}